// round 10
// baseline (speedup 1.0000x reference)
#include <cuda_runtime.h>
#include <math.h>
#include <stdint.h>

// Problem constants
#define B 8
#define A 100000
#define M 32
#define C 80
#define APB 320                      // anchors per block = threads (multiple of 20!)
#define NTILES ((A + APB - 1) / APB) // 313
#define NBLK (NTILES * B)            // 2504
#define V4PA (C / 4)                 // float4 per anchor = 20

// mask weight for contributing anchors: -0.75 * ln(2)
#define NEGW (-0.5198603854199589f)

// Device-global scratch (no allocation allowed)
__device__ float g_mask[NBLK * APB];    // per-anchor mask: NEGW or 0 (3.2MB)
__device__ float g_corr[NBLK];          // per-CTA positive-class corrections
__device__ float g_regp[NBLK];          // per-CTA regression partials
__device__ int   g_posp[NBLK];          // per-CTA positive counts
__device__ float g_clsp[NBLK];          // per-CTA sweep partials (kernel B)
__device__ unsigned int g_ticket = 0;

// ============================ Kernel A: assign ============================
// Pure-ALU anchor->GT assignment. No bulk memory traffic, runs at full
// occupancy, ~12-15us. Decoupling it from the sweep removes the per-warp
// phase serialization that capped DRAM at ~46% in the fused kernel.
__global__ __launch_bounds__(APB) void fl_assign_kernel(
    const float* __restrict__ cls,      // [B, A, C] (only positive-class reads)
    const float* __restrict__ reg,      // [B, A, 4]
    const float* __restrict__ anchors,  // [1, A, 4]
    const float* __restrict__ ann)      // [B, M, 6]
{
    __shared__ float4 s_box[M];
    __shared__ float2 s_misc[M];        // x = area_b, y = class id
    __shared__ float  s_rc[APB / 32];
    __shared__ float  s_rr[APB / 32];
    __shared__ int    s_rp[APB / 32];

    const int b   = blockIdx.y;
    const int a0  = blockIdx.x * APB;
    const int tid = threadIdx.x;
    const int blk = b * NTILES + blockIdx.x;

    if (tid < M) {
        const float* ap = ann + (b * M + tid) * 6;
        float x1 = ap[0], y1 = ap[1], x2 = ap[2], y2 = ap[3];
        const float cl = ap[4];
        float area = (x2 - x1) * (y2 - y1);
        if (cl == -1.0f) {
            // Invalid GT: far-away box -> inter == 0 for all anchors, area 0
            // -> identical classification/argmax behavior to reference's -1.
            x1 = 3e9f; y1 = 3e9f; x2 = 3e9f; y2 = 3e9f; area = 0.0f;
        }
        s_box[tid]  = make_float4(x1, y1, x2, y2);
        s_misc[tid] = make_float2(area, cl);
    }
    __syncthreads();

    float reg_partial = 0.0f;
    float corr_partial = 0.0f;
    int   pos_cnt = 0;
    float mask_val = 0.0f;

    const int a = a0 + tid;
    if (a < A) {
        const float4 av = *reinterpret_cast<const float4*>(anchors + a * 4);
        const float ax1 = av.x, ay1 = av.y, ax2 = av.z, ay2 = av.w;
        const float aw = ax2 - ax1;
        const float ah = ay2 - ay1;
        const float area_a = aw * ah;

        // IoU argmax via cross-multiplication (no division; ua >= area_a > 0)
        float b_in = -1.0f, b_ua = 1.0f;
        int   bi = 0;
        #pragma unroll 8
        for (int j = 0; j < M; j++) {
            const float4 g  = s_box[j];
            const float2 mi = s_misc[j];
            const float iw = fminf(ax2, g.z) - fmaxf(ax1, g.x);
            const float ih = fminf(ay2, g.w) - fmaxf(ay1, g.y);
            const float inter = fmaxf(iw, 0.0f) * fmaxf(ih, 0.0f);
            const float ua = (area_a + mi.x) - inter;
            const bool upd = (inter * b_ua > b_in * ua);
            if (upd) { b_in = inter; b_ua = ua; bi = j; }
        }

        const bool pos = (b_in >= 0.5f * b_ua);
        const bool ign = (!pos) && (b_in >= 0.4f * b_ua);
        mask_val = ign ? 0.0f : NEGW;

        if (pos) {
            pos_cnt = 1;
            const float4 g = s_box[bi];

            // positive-class correction: remove exactly what the sweep adds,
            // add the reference positive term.
            const int cid = (int)s_misc[bi].y;
            const float p_raw = cls[((size_t)b * A + a) * C + cid];
            const float sweep_term =
                NEGW * (p_raw * p_raw * __log2f(1.0f - p_raw));
            const float pc = fminf(fmaxf(p_raw, 1e-4f), 1.0f - 1e-4f);
            const float qc = 1.0f - pc;
            corr_partial = 0.25f * qc * qc * (-__logf(pc)) - sweep_term;

            // regression loss (smooth L1)
            float gw = g.z - g.x;
            float gh = g.w - g.y;
            const float gcx = g.x + 0.5f * gw;
            const float gcy = g.y + 0.5f * gh;
            gw = fmaxf(gw, 1.0f);
            gh = fmaxf(gh, 1.0f);
            const float acx = ax1 + 0.5f * aw;
            const float acy = ay1 + 0.5f * ah;

            const float t0 = ((gcx - acx) / aw) * 10.0f;
            const float t1 = ((gcy - acy) / ah) * 10.0f;
            const float t2 = __logf(gw / aw) * 5.0f;
            const float t3 = __logf(gh / ah) * 5.0f;

            const float4 r = *reinterpret_cast<const float4*>(reg + ((size_t)b * A + a) * 4);
            const float d0 = fabsf(t0 - r.x);
            const float d1 = fabsf(t1 - r.y);
            const float d2 = fabsf(t2 - r.z);
            const float d3 = fabsf(t3 - r.w);
            const float th = 1.0f / 9.0f;
            const float c2 = 0.5f / 9.0f;
            float rl = 0.0f;
            rl += (d0 <= th) ? 4.5f * d0 * d0 : d0 - c2;
            rl += (d1 <= th) ? 4.5f * d1 * d1 : d1 - c2;
            rl += (d2 <= th) ? 4.5f * d2 * d2 : d2 - c2;
            rl += (d3 <= th) ? 4.5f * d3 * d3 : d3 - c2;
            reg_partial = rl;
        }
    }
    g_mask[blk * APB + tid] = mask_val;   // coalesced STG

    // Block reduction of corr/reg/pos
    float cv = corr_partial;
    float rv = reg_partial;
    int   pv = pos_cnt;
    #pragma unroll
    for (int o = 16; o > 0; o >>= 1) {
        cv += __shfl_down_sync(0xFFFFFFFFu, cv, o);
        rv += __shfl_down_sync(0xFFFFFFFFu, rv, o);
        pv += __shfl_down_sync(0xFFFFFFFFu, pv, o);
    }
    const int wid = tid >> 5;
    const int lane = tid & 31;
    if (lane == 0) { s_rc[wid] = cv; s_rr[wid] = rv; s_rp[wid] = pv; }
    __syncthreads();
    if (tid == 0) {
        float c = 0.0f, r = 0.0f;
        int p = 0;
        #pragma unroll
        for (int i = 0; i < APB / 32; i++) { c += s_rc[i]; r += s_rr[i]; p += s_rp[i]; }
        g_corr[blk] = c;
        g_regp[blk] = r;
        g_posp[blk] = p;
    }
}

// ============================ Kernel B: sweep =============================
// Pure streaming focal-neg reduction over the 256MB class tensor. Masks are
// one coalesced load into shared; every warp issues loads continuously.
__global__ __launch_bounds__(APB) void fl_sweep_kernel(
    const float* __restrict__ cls,      // [B, A, C]
    float* __restrict__ out)            // [2]
{
    __shared__ float s_mask[APB];
    __shared__ float s_rc[APB / 32];
    __shared__ bool  s_last;

    const int b   = blockIdx.y;
    const int a0  = blockIdx.x * APB;
    const int tid = threadIdx.x;
    const int blk = b * NTILES + blockIdx.x;
    const int nA  = min(APB, A - a0);

    s_mask[tid] = g_mask[blk * APB + tid];
    __syncthreads();

    const float4* __restrict__ cp4 =
        reinterpret_cast<const float4*>(cls + ((size_t)b * A + a0) * C);
    const int mbase = tid / 20;   // APB = 16*20: anchor(tid+320k) = mbase+16k

    float acc0 = 0.f, acc1 = 0.f, acc2 = 0.f, acc3 = 0.f, acc4 = 0.f;

    // s = sum_i p_i^2 * log2(1 - p_i), FMA-chained, no clamps
    #define NT4S(v, s)                                                       \
    {                                                                        \
        const float l0 = __log2f(1.0f - (v).x);                              \
        const float l1 = __log2f(1.0f - (v).y);                              \
        const float l2 = __log2f(1.0f - (v).z);                              \
        const float l3 = __log2f(1.0f - (v).w);                              \
        const float q0 = (v).x * (v).x;                                      \
        const float q1 = (v).y * (v).y;                                      \
        const float q2 = (v).z * (v).z;                                      \
        const float q3 = (v).w * (v).w;                                      \
        s = fmaf(q0, l0, fmaf(q1, l1, fmaf(q2, l2, q3 * l3)));               \
    }

    if (nA == APB) {
        #define FL_GROUP(gbase)                                              \
        {                                                                    \
            const float4 v0 = __ldcs(cp4 + (tid + (gbase + 0) * APB));       \
            const float4 v1 = __ldcs(cp4 + (tid + (gbase + 1) * APB));       \
            const float4 v2 = __ldcs(cp4 + (tid + (gbase + 2) * APB));       \
            const float4 v3 = __ldcs(cp4 + (tid + (gbase + 3) * APB));       \
            const float4 v4 = __ldcs(cp4 + (tid + (gbase + 4) * APB));       \
            const float m0 = s_mask[mbase + 16 * (gbase + 0)];               \
            const float m1 = s_mask[mbase + 16 * (gbase + 1)];               \
            const float m2 = s_mask[mbase + 16 * (gbase + 2)];               \
            const float m3 = s_mask[mbase + 16 * (gbase + 3)];               \
            const float m4 = s_mask[mbase + 16 * (gbase + 4)];               \
            float s0, s1, s2, s3, s4;                                        \
            NT4S(v0, s0) NT4S(v1, s1) NT4S(v2, s2) NT4S(v3, s3) NT4S(v4, s4) \
            acc0 = fmaf(m0, s0, acc0);                                       \
            acc1 = fmaf(m1, s1, acc1);                                       \
            acc2 = fmaf(m2, s2, acc2);                                       \
            acc3 = fmaf(m3, s3, acc3);                                       \
            acc4 = fmaf(m4, s4, acc4);                                       \
        }
        FL_GROUP(0)
        FL_GROUP(5)
        FL_GROUP(10)
        FL_GROUP(15)
        #undef FL_GROUP
    } else {
        const int n4 = nA * V4PA;
        for (int k = 0; k < V4PA; k++) {
            const int i4 = tid + k * APB;
            if (i4 < n4) {
                const float4 v = __ldcs(cp4 + i4);
                const float m = s_mask[mbase + 16 * k];
                float s;
                NT4S(v, s)
                acc0 = fmaf(m, s, acc0);
            }
        }
    }
    #undef NT4S

    float cv = ((acc0 + acc1) + (acc2 + acc3)) + acc4;
    #pragma unroll
    for (int o = 16; o > 0; o >>= 1)
        cv += __shfl_down_sync(0xFFFFFFFFu, cv, o);
    const int wid = tid >> 5;
    const int lane = tid & 31;
    if (lane == 0) s_rc[wid] = cv;
    __syncthreads();

    if (tid == 0) {
        float c = 0.0f;
        #pragma unroll
        for (int i = 0; i < APB / 32; i++) c += s_rc[i];
        g_clsp[blk] = c;
        __threadfence();
        const unsigned int t = atomicAdd(&g_ticket, 1u);
        s_last = (t == (unsigned int)(NBLK - 1));
    }
    __syncthreads();

    // Last CTA: reduce sweep partials + kernel A partials, write output.
    if (s_last) {
        __shared__ double f_c[B][APB / 32];
        __shared__ double f_r[B][APB / 32];
        __shared__ int    f_p[B][APB / 32];

        #pragma unroll
        for (int img = 0; img < B; img++) {
            double c = 0.0, r = 0.0;
            int p = 0;
            for (int i = tid; i < NTILES; i += APB) {
                const int idx = img * NTILES + i;
                c += (double)g_clsp[idx] + (double)g_corr[idx];
                r += (double)g_regp[idx];
                p += g_posp[idx];
            }
            #pragma unroll
            for (int o = 16; o > 0; o >>= 1) {
                c += __shfl_down_sync(0xFFFFFFFFu, c, o);
                r += __shfl_down_sync(0xFFFFFFFFu, r, o);
                p += __shfl_down_sync(0xFFFFFFFFu, p, o);
            }
            if (lane == 0) { f_c[img][wid] = c; f_r[img][wid] = r; f_p[img][wid] = p; }
        }
        __syncthreads();
        if (tid == 0) {
            double cl = 0.0, rl = 0.0;
            #pragma unroll
            for (int img = 0; img < B; img++) {
                double c = 0.0, r = 0.0;
                int p = 0;
                #pragma unroll
                for (int i = 0; i < APB / 32; i++) {
                    c += f_c[img][i]; r += f_r[img][i]; p += f_p[img][i];
                }
                const double d = (p < 1) ? 1.0 : (double)p;
                cl += c / d;
                if (p > 0) rl += r / (4.0 * d);
            }
            out[0] = (float)(cl / (double)B);
            out[1] = (float)(rl / (double)B);
            g_ticket = 0;  // reset for next graph replay
        }
    }
}

extern "C" void kernel_launch(void* const* d_in, const int* in_sizes, int n_in,
                              void* d_out, int out_size) {
    const float* cls = nullptr;
    const float* reg = nullptr;
    const float* anc = nullptr;
    const float* ann = nullptr;
    for (int i = 0; i < n_in; i++) {
        switch (in_sizes[i]) {
            case B * A * C:  cls = (const float*)d_in[i]; break;  // 64,000,000
            case B * A * 4:  reg = (const float*)d_in[i]; break;  //  3,200,000
            case A * 4:      anc = (const float*)d_in[i]; break;  //    400,000
            case B * M * 6:  ann = (const float*)d_in[i]; break;  //      1,536
            default: break;
        }
    }
    float* out = (float*)d_out;

    dim3 grid(NTILES, B);
    fl_assign_kernel<<<grid, APB>>>(cls, reg, anc, ann);
    fl_sweep_kernel<<<grid, APB>>>(cls, out);
}

// round 11
// speedup vs baseline: 1.0780x; 1.0780x over previous
#include <cuda_runtime.h>
#include <math.h>
#include <stdint.h>

// Problem constants
#define B 8
#define A 100000
#define M 32
#define C 80
#define APB 320                      // threads per block; anchors per tile (16*20)
#define NTILES ((A + APB - 1) / APB) // 313
#define NBLK (NTILES * B)            // 2504 tiles total
#define NASSIGN NTILES               // 313 assign CTAs (each: 1 anchor range x 8 images)
#define GRID (NASSIGN + NBLK)        // 2817
#define V4PA (C / 4)                 // float4 per anchor = 20

// mask weight for contributing anchors: -0.75 * ln(2)
#define NEGW (-0.5198603854199589f)

// Device-global scratch (no allocation allowed)
__device__ float    g_mask[NBLK * APB];  // per-anchor mask (3.2MB)
__device__ float    g_corr[NBLK];        // per-tile positive-class corrections
__device__ float    g_regp[NBLK];        // per-tile regression partials
__device__ int      g_posp[NBLK];        // per-tile positive counts
__device__ float    g_clsp[NBLK];        // per-tile sweep partials
__device__ unsigned g_flag[NBLK];        // tile-ready flags (reset by finalize)
__device__ unsigned g_ticket = 0;

__device__ __forceinline__ unsigned ld_acquire_gpu(const unsigned* p) {
    unsigned v;
    asm volatile("ld.global.acquire.gpu.u32 %0, [%1];" : "=r"(v) : "l"(p) : "memory");
    return v;
}

__global__ __launch_bounds__(APB, 4) void fl_ws_kernel(
    const float* __restrict__ cls,      // [B, A, C]
    const float* __restrict__ reg,      // [B, A, 4]
    const float* __restrict__ anchors,  // [1, A, 4]
    const float* __restrict__ ann,      // [B, M, 6]
    float* __restrict__ out)            // [2]
{
    __shared__ float4 s_box8[B][M];      // all 8 images' GT boxes (assign role)
    __shared__ float2 s_misc8[B][M];     // x = area_b, y = class id
    __shared__ float  s_mask[APB];       // sweep role
    __shared__ float  s_rc[APB / 32];
    __shared__ float  s_rr[APB / 32];
    __shared__ int    s_rp[APB / 32];
    __shared__ bool   s_last;

    const int tid  = threadIdx.x;
    const int wid  = tid >> 5;
    const int lane = tid & 31;
    const int bid  = blockIdx.x;

    if (bid < NASSIGN) {
        // ===================== ASSIGN role =====================
        const int r  = bid;            // anchor-range index (tile column)
        const int a0 = r * APB;
        const int a  = a0 + tid;
        const bool va = (a < A);

        // Stage ALL 8 images' annotations (256 threads, one GT each)
        if (tid < B * M) {
            const int img = tid >> 5;
            const int j   = tid & 31;
            const float* ap = ann + (img * M + j) * 6;
            float x1 = ap[0], y1 = ap[1], x2 = ap[2], y2 = ap[3];
            const float cl = ap[4];
            float area = (x2 - x1) * (y2 - y1);
            if (cl == -1.0f) {
                // Invalid GT: far-away box -> inter == 0 always, area 0 ->
                // identical classification/argmax behavior to iou = -1.
                x1 = 3e9f; y1 = 3e9f; x2 = 3e9f; y2 = 3e9f; area = 0.0f;
            }
            s_box8[img][j]  = make_float4(x1, y1, x2, y2);
            s_misc8[img][j] = make_float2(area, cl);
        }
        __syncthreads();

        // Anchor geometry loaded ONCE, reused for all 8 images
        float ax1 = 0.f, ay1 = 0.f, ax2 = 0.f, ay2 = 0.f;
        float aw = 1.f, ah = 1.f, area_a = 1.f, acx = 0.f, acy = 0.f;
        if (va) {
            const float4 av = *reinterpret_cast<const float4*>(anchors + a * 4);
            ax1 = av.x; ay1 = av.y; ax2 = av.z; ay2 = av.w;
            aw = ax2 - ax1; ah = ay2 - ay1;
            area_a = aw * ah;
            acx = ax1 + 0.5f * aw;
            acy = ay1 + 0.5f * ah;
        }

        for (int p = 0; p < B; p++) {
            const int t = p * NASSIGN + r;   // tile id = b*NTILES + r
            __syncthreads();                 // reuse of s_rc/s_rr/s_rp

            float mask_val = 0.0f;
            float corr = 0.0f, regl = 0.0f;
            int   posc = 0;

            if (va) {
                // IoU argmax via cross-multiplication (no division)
                float b_in = -1.0f, b_ua = 1.0f;
                int   bi = 0;
                #pragma unroll 8
                for (int j = 0; j < M; j++) {
                    const float4 g  = s_box8[p][j];
                    const float2 mi = s_misc8[p][j];
                    const float iw = fminf(ax2, g.z) - fmaxf(ax1, g.x);
                    const float ih = fminf(ay2, g.w) - fmaxf(ay1, g.y);
                    const float inter = fmaxf(iw, 0.0f) * fmaxf(ih, 0.0f);
                    const float ua = (area_a + mi.x) - inter;
                    if (inter * b_ua > b_in * ua) { b_in = inter; b_ua = ua; bi = j; }
                }

                const bool pos = (b_in >= 0.5f * b_ua);
                const bool ign = (!pos) && (b_in >= 0.4f * b_ua);
                mask_val = ign ? 0.0f : NEGW;

                if (pos) {
                    posc = 1;
                    const float4 g = s_box8[p][bi];

                    // positive-class correction (remove sweep term, add ref term)
                    const int cid = (int)s_misc8[p][bi].y;
                    const float p_raw = cls[((size_t)p * A + a) * C + cid];
                    const float sweep_term =
                        NEGW * (p_raw * p_raw * __log2f(1.0f - p_raw));
                    const float pc = fminf(fmaxf(p_raw, 1e-4f), 1.0f - 1e-4f);
                    const float qc = 1.0f - pc;
                    corr = 0.25f * qc * qc * (-__logf(pc)) - sweep_term;

                    // regression loss (smooth L1)
                    float gw = g.z - g.x;
                    float gh = g.w - g.y;
                    const float gcx = g.x + 0.5f * gw;
                    const float gcy = g.y + 0.5f * gh;
                    gw = fmaxf(gw, 1.0f);
                    gh = fmaxf(gh, 1.0f);
                    const float t0 = ((gcx - acx) / aw) * 10.0f;
                    const float t1 = ((gcy - acy) / ah) * 10.0f;
                    const float t2 = __logf(gw / aw) * 5.0f;
                    const float t3 = __logf(gh / ah) * 5.0f;
                    const float4 rv4 = *reinterpret_cast<const float4*>(
                        reg + ((size_t)p * A + a) * 4);
                    const float d0 = fabsf(t0 - rv4.x);
                    const float d1 = fabsf(t1 - rv4.y);
                    const float d2 = fabsf(t2 - rv4.z);
                    const float d3 = fabsf(t3 - rv4.w);
                    const float th = 1.0f / 9.0f;
                    const float c2 = 0.5f / 9.0f;
                    regl  = (d0 <= th) ? 4.5f * d0 * d0 : d0 - c2;
                    regl += (d1 <= th) ? 4.5f * d1 * d1 : d1 - c2;
                    regl += (d2 <= th) ? 4.5f * d2 * d2 : d2 - c2;
                    regl += (d3 <= th) ? 4.5f * d3 * d3 : d3 - c2;
                }
            }
            g_mask[(size_t)t * APB + tid] = mask_val;   // coalesced

            // Block reduce corr/reg/pos for this tile
            float cv = corr, rv = regl;
            int pv = posc;
            #pragma unroll
            for (int o = 16; o > 0; o >>= 1) {
                cv += __shfl_down_sync(0xFFFFFFFFu, cv, o);
                rv += __shfl_down_sync(0xFFFFFFFFu, rv, o);
                pv += __shfl_down_sync(0xFFFFFFFFu, pv, o);
            }
            if (lane == 0) { s_rc[wid] = cv; s_rr[wid] = rv; s_rp[wid] = pv; }
            __syncthreads();
            if (tid == 0) {
                float c = 0.0f, rr = 0.0f;
                int pp = 0;
                #pragma unroll
                for (int i = 0; i < APB / 32; i++) {
                    c += s_rc[i]; rr += s_rr[i]; pp += s_rp[i];
                }
                g_corr[t] = c;
                g_regp[t] = rr;
                g_posp[t] = pp;
                __threadfence();                 // publish mask + partials
                atomicExch(&g_flag[t], 1u);      // release tile t
            }
        }
        return;
    }

    // ===================== SWEEP role =====================
    const int t   = bid - NASSIGN;      // tile id
    const int b   = t / NTILES;
    const int tx  = t - b * NTILES;
    const int a0  = tx * APB;
    const int nA  = min(APB, A - a0);

    if (tid == 0) {
        while (ld_acquire_gpu(&g_flag[t]) == 0u) { __nanosleep(200); }
    }
    __syncthreads();
    s_mask[tid] = g_mask[(size_t)t * APB + tid];
    __syncthreads();

    const float4* __restrict__ cp4 =
        reinterpret_cast<const float4*>(cls + ((size_t)b * A + a0) * C);
    const int mbase = tid / 20;   // APB = 16*20: anchor(tid+320k) = mbase+16k

    float acc0 = 0.f, acc1 = 0.f, acc2 = 0.f, acc3 = 0.f;

    // s = sum_i p_i^2 * log2(1 - p_i), FMA-chained
    #define NT4S(v, s)                                                       \
    {                                                                        \
        const float l0 = __log2f(1.0f - (v).x);                              \
        const float l1 = __log2f(1.0f - (v).y);                              \
        const float l2 = __log2f(1.0f - (v).z);                              \
        const float l3 = __log2f(1.0f - (v).w);                              \
        const float q0 = (v).x * (v).x;                                      \
        const float q1 = (v).y * (v).y;                                      \
        const float q2 = (v).z * (v).z;                                      \
        const float q3 = (v).w * (v).w;                                      \
        s = fmaf(q0, l0, fmaf(q1, l1, fmaf(q2, l2, q3 * l3)));               \
    }

    if (nA == APB) {
        // 5 groups of 4 outstanding LDG.128 (fits the ~51-reg budget of
        // __launch_bounds__(320,4) -> 40 warps/SM x MLP 4 = 80KB in flight/SM)
        #define FL_GROUP4(gbase)                                             \
        {                                                                    \
            const float4 v0 = __ldcs(cp4 + (tid + (gbase + 0) * APB));       \
            const float4 v1 = __ldcs(cp4 + (tid + (gbase + 1) * APB));       \
            const float4 v2 = __ldcs(cp4 + (tid + (gbase + 2) * APB));       \
            const float4 v3 = __ldcs(cp4 + (tid + (gbase + 3) * APB));       \
            const float m0 = s_mask[mbase + 16 * (gbase + 0)];               \
            const float m1 = s_mask[mbase + 16 * (gbase + 1)];               \
            const float m2 = s_mask[mbase + 16 * (gbase + 2)];               \
            const float m3 = s_mask[mbase + 16 * (gbase + 3)];               \
            float s0, s1, s2, s3;                                            \
            NT4S(v0, s0) NT4S(v1, s1) NT4S(v2, s2) NT4S(v3, s3)              \
            acc0 = fmaf(m0, s0, acc0);                                       \
            acc1 = fmaf(m1, s1, acc1);                                       \
            acc2 = fmaf(m2, s2, acc2);                                       \
            acc3 = fmaf(m3, s3, acc3);                                       \
        }
        FL_GROUP4(0)
        FL_GROUP4(4)
        FL_GROUP4(8)
        FL_GROUP4(12)
        FL_GROUP4(16)
        #undef FL_GROUP4
    } else {
        const int n4 = nA * V4PA;
        for (int k = 0; k < V4PA; k++) {
            const int i4 = tid + k * APB;
            if (i4 < n4) {
                const float4 v = __ldcs(cp4 + i4);
                const float m = s_mask[mbase + 16 * k];
                float s;
                NT4S(v, s)
                acc0 = fmaf(m, s, acc0);
            }
        }
    }
    #undef NT4S

    float cv = (acc0 + acc1) + (acc2 + acc3);
    #pragma unroll
    for (int o = 16; o > 0; o >>= 1)
        cv += __shfl_down_sync(0xFFFFFFFFu, cv, o);
    if (lane == 0) s_rc[wid] = cv;
    __syncthreads();

    if (tid == 0) {
        float c = 0.0f;
        #pragma unroll
        for (int i = 0; i < APB / 32; i++) c += s_rc[i];
        g_clsp[t] = c;
        __threadfence();
        const unsigned tk = atomicAdd(&g_ticket, 1u);
        s_last = (tk == (unsigned)(NBLK - 1));
    }
    __syncthreads();

    // Last sweep CTA: reduce everything, write output, reset flags+ticket.
    if (s_last) {
        __shared__ double f_c[B][APB / 32];
        __shared__ double f_r[B][APB / 32];
        __shared__ int    f_p[B][APB / 32];

        #pragma unroll
        for (int img = 0; img < B; img++) {
            double c = 0.0, r = 0.0;
            int p = 0;
            for (int i = tid; i < NTILES; i += APB) {
                const int idx = img * NTILES + i;
                c += (double)g_clsp[idx] + (double)g_corr[idx];
                r += (double)g_regp[idx];
                p += g_posp[idx];
            }
            #pragma unroll
            for (int o = 16; o > 0; o >>= 1) {
                c += __shfl_down_sync(0xFFFFFFFFu, c, o);
                r += __shfl_down_sync(0xFFFFFFFFu, r, o);
                p += __shfl_down_sync(0xFFFFFFFFu, p, o);
            }
            if (lane == 0) { f_c[img][wid] = c; f_r[img][wid] = r; f_p[img][wid] = p; }
        }
        __syncthreads();
        // reset flags for the next graph replay (all tiles already consumed)
        for (int i = tid; i < NBLK; i += APB) g_flag[i] = 0u;
        if (tid == 0) {
            double cl = 0.0, rl = 0.0;
            #pragma unroll
            for (int img = 0; img < B; img++) {
                double c = 0.0, r = 0.0;
                int p = 0;
                #pragma unroll
                for (int i = 0; i < APB / 32; i++) {
                    c += f_c[img][i]; r += f_r[img][i]; p += f_p[img][i];
                }
                const double d = (p < 1) ? 1.0 : (double)p;
                cl += c / d;
                if (p > 0) rl += r / (4.0 * d);
            }
            out[0] = (float)(cl / (double)B);
            out[1] = (float)(rl / (double)B);
            g_ticket = 0;
        }
    }
}

extern "C" void kernel_launch(void* const* d_in, const int* in_sizes, int n_in,
                              void* d_out, int out_size) {
    const float* cls = nullptr;
    const float* reg = nullptr;
    const float* anc = nullptr;
    const float* ann = nullptr;
    for (int i = 0; i < n_in; i++) {
        switch (in_sizes[i]) {
            case B * A * C:  cls = (const float*)d_in[i]; break;  // 64,000,000
            case B * A * 4:  reg = (const float*)d_in[i]; break;  //  3,200,000
            case A * 4:      anc = (const float*)d_in[i]; break;  //    400,000
            case B * M * 6:  ann = (const float*)d_in[i]; break;  //      1,536
            default: break;
        }
    }
    float* out = (float*)d_out;

    fl_ws_kernel<<<GRID, APB>>>(cls, reg, anc, ann, out);
}

// round 12
// speedup vs baseline: 1.0998x; 1.0202x over previous
#include <cuda_runtime.h>
#include <math.h>
#include <stdint.h>

// Problem constants
#define B 8
#define A 100000
#define M 32
#define C 80
#define APB 320                      // threads = anchors per tile (16*20)
#define NTILES ((A + APB - 1) / APB) // 313
#define NBLK (NTILES * B)            // 2504
#define V4PA (C / 4)                 // float4 per anchor = 20
#define NFLAT (APB * V4PA)           // 6400 s-values per tile

// mask weight for contributing anchors: -0.75 * ln(2)
#define NEGW (-0.5198603854199589f)

// pad shared index to break 4-way bank conflicts in the combine gather
#define SPAD(i) ((i) + ((i) >> 5))

// Per-CTA partials + finalize ticket (device globals; no allocation allowed)
__device__ float g_cls_part[NBLK];
__device__ float g_reg_part[NBLK];
__device__ int   g_pos_part[NBLK];
__device__ unsigned int g_ticket = 0;

__global__ __launch_bounds__(APB, 3) void fl_pipe_kernel(
    const float* __restrict__ cls,      // [B, A, C]
    const float* __restrict__ reg,      // [B, A, 4]
    const float* __restrict__ anchors,  // [1, A, 4]
    const float* __restrict__ ann,      // [B, M, 6]
    float* __restrict__ out)            // [2]
{
    __shared__ float  s_flat[NFLAT + NFLAT / 32];  // unmasked per-chunk sums
    __shared__ float4 s_box[M];
    __shared__ float2 s_misc[M];         // x = area_b, y = class id
    __shared__ float  s_mask[APB];       // edge-tile path only
    __shared__ float  s_rc[APB / 32];
    __shared__ float  s_rr[APB / 32];
    __shared__ int    s_rp[APB / 32];
    __shared__ bool   s_last;

    const int b    = blockIdx.y;
    const int a0   = blockIdx.x * APB;
    const int tid  = threadIdx.x;
    const int wid  = tid >> 5;
    const int lane = tid & 31;
    const int blk  = b * NTILES + blockIdx.x;
    const int nA   = min(APB, A - a0);
    const bool full = (nA == APB);

    const float4* __restrict__ cp4 =
        reinterpret_cast<const float4*>(cls + ((size_t)b * A + a0) * C);

    // ---- issue first 8 class loads IMMEDIATELY (no dependency on anything) ----
    float4 v0, v1, v2, v3, v4, v5, v6, v7;
    if (full) {
        v0 = __ldcs(cp4 + (tid + 0 * APB));
        v1 = __ldcs(cp4 + (tid + 1 * APB));
        v2 = __ldcs(cp4 + (tid + 2 * APB));
        v3 = __ldcs(cp4 + (tid + 3 * APB));
        v4 = __ldcs(cp4 + (tid + 4 * APB));
        v5 = __ldcs(cp4 + (tid + 5 * APB));
        v6 = __ldcs(cp4 + (tid + 6 * APB));
        v7 = __ldcs(cp4 + (tid + 7 * APB));
    }

    // stage annotations
    if (tid < M) {
        const float* ap = ann + (b * M + tid) * 6;
        float x1 = ap[0], y1 = ap[1], x2 = ap[2], y2 = ap[3];
        const float cl = ap[4];
        float area = (x2 - x1) * (y2 - y1);
        if (cl == -1.0f) {
            // Invalid GT: far-away box -> inter == 0 always, area 0 ->
            // identical classification/argmax behavior to reference's iou=-1.
            x1 = 3e9f; y1 = 3e9f; x2 = 3e9f; y2 = 3e9f; area = 0.0f;
        }
        s_box[tid]  = make_float4(x1, y1, x2, y2);
        s_misc[tid] = make_float2(area, cl);
    }
    __syncthreads();

    // anchor geometry (kept live through the pipeline)
    const int a = a0 + tid;
    float ax1 = 0.f, ay1 = 0.f, ax2 = 0.f, ay2 = 0.f;
    float aw = 1.f, ah = 1.f, area_a = 1.f;
    if (a < A) {
        const float4 av = *reinterpret_cast<const float4*>(anchors + a * 4);
        ax1 = av.x; ay1 = av.y; ax2 = av.z; ay2 = av.w;
        aw = ax2 - ax1; ah = ay2 - ay1;
        area_a = aw * ah;
    }

    float b_in = -1.0f, b_ua = 1.0f;
    int   bi = 0;

    // one IoU iteration (cross-multiplied compare; no division)
    #define IOU_ITER(j)                                                       \
    {                                                                         \
        const float4 g  = s_box[j];                                           \
        const float2 mi = s_misc[j];                                          \
        const float iw = fminf(ax2, g.z) - fmaxf(ax1, g.x);                   \
        const float ih = fminf(ay2, g.w) - fmaxf(ay1, g.y);                   \
        const float inter = fmaxf(iw, 0.0f) * fmaxf(ih, 0.0f);                \
        const float ua = (area_a + mi.x) - inter;                             \
        if (inter * b_ua > b_in * ua) { b_in = inter; b_ua = ua; bi = j; }    \
    }
    #define IOU_CHUNK(j0, j1)                                                 \
    {                                                                         \
        _Pragma("unroll")                                                     \
        for (int j = (j0); j < (j1); j++) IOU_ITER(j)                         \
    }

    // consume one float4 -> unmasked sum -> shared scratch
    #define CONSUME(v, k)                                                     \
    {                                                                         \
        const float l0 = __log2f(1.0f - (v).x);                               \
        const float l1 = __log2f(1.0f - (v).y);                               \
        const float l2 = __log2f(1.0f - (v).z);                               \
        const float l3 = __log2f(1.0f - (v).w);                               \
        const float q0 = (v).x * (v).x;                                       \
        const float q1 = (v).y * (v).y;                                       \
        const float q2 = (v).z * (v).z;                                       \
        const float q3 = (v).w * (v).w;                                       \
        s_flat[SPAD((k) * APB + tid)] =                                       \
            fmaf(q0, l0, fmaf(q1, l1, fmaf(q2, l2, q3 * l3)));                \
    }

    if (full) {
        // software pipeline: keep 4-8 LDG.128 in flight; IoU ALU covers latency
        IOU_CHUNK(0, 5)
        CONSUME(v0, 0) CONSUME(v1, 1) CONSUME(v2, 2) CONSUME(v3, 3)
        v0 = __ldcs(cp4 + (tid +  8 * APB));
        v1 = __ldcs(cp4 + (tid +  9 * APB));
        v2 = __ldcs(cp4 + (tid + 10 * APB));
        v3 = __ldcs(cp4 + (tid + 11 * APB));
        IOU_CHUNK(5, 10)
        CONSUME(v4, 4) CONSUME(v5, 5) CONSUME(v6, 6) CONSUME(v7, 7)
        v4 = __ldcs(cp4 + (tid + 12 * APB));
        v5 = __ldcs(cp4 + (tid + 13 * APB));
        v6 = __ldcs(cp4 + (tid + 14 * APB));
        v7 = __ldcs(cp4 + (tid + 15 * APB));
        IOU_CHUNK(10, 15)
        CONSUME(v0, 8) CONSUME(v1, 9) CONSUME(v2, 10) CONSUME(v3, 11)
        v0 = __ldcs(cp4 + (tid + 16 * APB));
        v1 = __ldcs(cp4 + (tid + 17 * APB));
        v2 = __ldcs(cp4 + (tid + 18 * APB));
        v3 = __ldcs(cp4 + (tid + 19 * APB));
        IOU_CHUNK(15, 21)
        CONSUME(v4, 12) CONSUME(v5, 13) CONSUME(v6, 14) CONSUME(v7, 15)
        IOU_CHUNK(21, 32)
        CONSUME(v0, 16) CONSUME(v1, 17) CONSUME(v2, 18) CONSUME(v3, 19)
    } else {
        // edge tiles (8 of 2504): plain order, guarded
        IOU_CHUNK(0, 32)
    }

    // classify this thread's anchor
    const bool va  = (a < A);
    const bool pos = va && (b_in >= 0.5f * b_ua);
    const bool ign = va && (!pos) && (b_in >= 0.4f * b_ua);
    const float mask_val = (va && !ign) ? NEGW : 0.0f;

    float cls_partial = 0.0f;
    float reg_partial = 0.0f;
    int   pos_cnt = 0;

    if (pos) {
        pos_cnt = 1;
        const float4 g = s_box[bi];

        // positive-class correction: remove exactly the unmasked sweep term,
        // add the reference positive term.
        const int cid = (int)s_misc[bi].y;
        const float p_raw = cls[((size_t)b * A + a) * C + cid];
        const float sweep_term =
            NEGW * (p_raw * p_raw * __log2f(1.0f - p_raw));
        const float pc = fminf(fmaxf(p_raw, 1e-4f), 1.0f - 1e-4f);
        const float qc = 1.0f - pc;
        cls_partial += 0.25f * qc * qc * (-__logf(pc)) - sweep_term;

        // regression loss (smooth L1)
        float gw = g.z - g.x;
        float gh = g.w - g.y;
        const float gcx = g.x + 0.5f * gw;
        const float gcy = g.y + 0.5f * gh;
        gw = fmaxf(gw, 1.0f);
        gh = fmaxf(gh, 1.0f);
        const float acx = ax1 + 0.5f * aw;
        const float acy = ay1 + 0.5f * ah;
        const float t0 = ((gcx - acx) / aw) * 10.0f;
        const float t1 = ((gcy - acy) / ah) * 10.0f;
        const float t2 = __logf(gw / aw) * 5.0f;
        const float t3 = __logf(gh / ah) * 5.0f;
        const float4 r = *reinterpret_cast<const float4*>(reg + ((size_t)b * A + a) * 4);
        const float d0 = fabsf(t0 - r.x);
        const float d1 = fabsf(t1 - r.y);
        const float d2 = fabsf(t2 - r.z);
        const float d3 = fabsf(t3 - r.w);
        const float th = 1.0f / 9.0f;
        const float c2 = 0.5f / 9.0f;
        reg_partial  = (d0 <= th) ? 4.5f * d0 * d0 : d0 - c2;
        reg_partial += (d1 <= th) ? 4.5f * d1 * d1 : d1 - c2;
        reg_partial += (d2 <= th) ? 4.5f * d2 * d2 : d2 - c2;
        reg_partial += (d3 <= th) ? 4.5f * d3 * d3 : d3 - c2;
    }

    if (full) {
        __syncthreads();   // all s_flat writes visible
        // combine: thread tid gathers its OWN anchor's 20 unmasked sums
        float S = 0.0f;
        #pragma unroll
        for (int j = 0; j < V4PA; j++)
            S += s_flat[SPAD(V4PA * tid + j)];
        cls_partial = fmaf(mask_val, S, cls_partial);
    } else {
        s_mask[tid] = mask_val;
        __syncthreads();
        const int mbase = tid / 20;
        const int n4 = nA * V4PA;
        float acc = 0.0f;
        for (int k = 0; k < V4PA; k++) {
            const int i4 = tid + k * APB;
            if (i4 < n4) {
                const float4 v = __ldcs(cp4 + i4);
                const float l0 = __log2f(1.0f - v.x);
                const float l1 = __log2f(1.0f - v.y);
                const float l2 = __log2f(1.0f - v.z);
                const float l3 = __log2f(1.0f - v.w);
                const float s = fmaf(v.x * v.x, l0, fmaf(v.y * v.y, l1,
                                fmaf(v.z * v.z, l2, (v.w * v.w) * l3)));
                acc = fmaf(s_mask[mbase + 16 * k], s, acc);
            }
        }
        cls_partial += acc;
    }
    #undef IOU_ITER
    #undef IOU_CHUNK
    #undef CONSUME

    // Block reduction -> per-CTA partials
    float cv = cls_partial;
    float rv = reg_partial;
    int   pv = pos_cnt;
    #pragma unroll
    for (int o = 16; o > 0; o >>= 1) {
        cv += __shfl_down_sync(0xFFFFFFFFu, cv, o);
        rv += __shfl_down_sync(0xFFFFFFFFu, rv, o);
        pv += __shfl_down_sync(0xFFFFFFFFu, pv, o);
    }
    if (lane == 0) { s_rc[wid] = cv; s_rr[wid] = rv; s_rp[wid] = pv; }
    __syncthreads();

    if (tid == 0) {
        float c = 0.0f, r = 0.0f;
        int p = 0;
        #pragma unroll
        for (int i = 0; i < APB / 32; i++) { c += s_rc[i]; r += s_rr[i]; p += s_rp[i]; }
        g_cls_part[blk] = c;
        g_reg_part[blk] = r;
        g_pos_part[blk] = p;
        __threadfence();
        const unsigned int t = atomicAdd(&g_ticket, 1u);
        s_last = (t == (unsigned int)(NBLK - 1));
    }
    __syncthreads();

    // Last CTA reduces all per-CTA partials and writes the output.
    if (s_last) {
        __shared__ double f_c[B][APB / 32];
        __shared__ double f_r[B][APB / 32];
        __shared__ int    f_p[B][APB / 32];

        #pragma unroll
        for (int img = 0; img < B; img++) {
            double c = 0.0, r = 0.0;
            int p = 0;
            for (int i = tid; i < NTILES; i += APB) {
                const int idx = img * NTILES + i;
                c += (double)g_cls_part[idx];
                r += (double)g_reg_part[idx];
                p += g_pos_part[idx];
            }
            #pragma unroll
            for (int o = 16; o > 0; o >>= 1) {
                c += __shfl_down_sync(0xFFFFFFFFu, c, o);
                r += __shfl_down_sync(0xFFFFFFFFu, r, o);
                p += __shfl_down_sync(0xFFFFFFFFu, p, o);
            }
            if (lane == 0) { f_c[img][wid] = c; f_r[img][wid] = r; f_p[img][wid] = p; }
        }
        __syncthreads();
        if (tid == 0) {
            double cl = 0.0, rl = 0.0;
            #pragma unroll
            for (int img = 0; img < B; img++) {
                double c = 0.0, r = 0.0;
                int p = 0;
                #pragma unroll
                for (int i = 0; i < APB / 32; i++) {
                    c += f_c[img][i]; r += f_r[img][i]; p += f_p[img][i];
                }
                const double d = (p < 1) ? 1.0 : (double)p;
                cl += c / d;
                if (p > 0) rl += r / (4.0 * d);
            }
            out[0] = (float)(cl / (double)B);
            out[1] = (float)(rl / (double)B);
            g_ticket = 0;  // reset for the next graph replay
        }
    }
}

extern "C" void kernel_launch(void* const* d_in, const int* in_sizes, int n_in,
                              void* d_out, int out_size) {
    const float* cls = nullptr;
    const float* reg = nullptr;
    const float* anc = nullptr;
    const float* ann = nullptr;
    for (int i = 0; i < n_in; i++) {
        switch (in_sizes[i]) {
            case B * A * C:  cls = (const float*)d_in[i]; break;  // 64,000,000
            case B * A * 4:  reg = (const float*)d_in[i]; break;  //  3,200,000
            case A * 4:      anc = (const float*)d_in[i]; break;  //    400,000
            case B * M * 6:  ann = (const float*)d_in[i]; break;  //      1,536
            default: break;
        }
    }
    float* out = (float*)d_out;

    dim3 grid(NTILES, B);
    fl_pipe_kernel<<<grid, APB>>>(cls, reg, anc, ann, out);
}

// round 13
// speedup vs baseline: 1.2553x; 1.1414x over previous
#include <cuda_runtime.h>
#include <math.h>
#include <stdint.h>

// Problem constants
#define B 8
#define A 100000
#define M 32
#define C 80
#define APB 320                      // threads = anchors per tile (16*20)
#define NTILES ((A + APB - 1) / APB) // 313
#define NBLK (NTILES * B)            // 2504
#define V4PA (C / 4)                 // float4 per anchor = 20
#define CHA 80                       // anchors per chunk
#define CHF (CHA * C)                // 6400 floats per chunk
#define CHB (CHF * 4)                // 25600 bytes per chunk
#define CH4 (CHF / 4)                // 1600 float4 per chunk
#define SMEM_DYN (2 * CHB)           // 51200 bytes (double buffer)

// mask weight for contributing anchors: -0.75 * ln(2)
#define NEGW (-0.5198603854199589f)

// Per-CTA partials + finalize ticket (device globals; no allocation allowed)
__device__ float g_cls_part[NBLK];
__device__ float g_reg_part[NBLK];
__device__ int   g_pos_part[NBLK];
__device__ unsigned int g_ticket = 0;

__device__ __forceinline__ uint32_t s2u(const void* p) {
    uint32_t r;
    asm("{ .reg .u64 t; cvta.to.shared.u64 t, %1; cvt.u32.u64 %0, t; }"
        : "=r"(r) : "l"(p));
    return r;
}
__device__ __forceinline__ void mbar_init(uint32_t mbar, uint32_t cnt) {
    asm volatile("mbarrier.init.shared.b64 [%0], %1;" :: "r"(mbar), "r"(cnt) : "memory");
}
__device__ __forceinline__ void mbar_expect_tx(uint32_t mbar, uint32_t bytes) {
    asm volatile("mbarrier.arrive.expect_tx.shared.b64 _, [%0], %1;"
                 :: "r"(mbar), "r"(bytes) : "memory");
}
__device__ __forceinline__ void bulk_g2s(uint32_t dst, const void* src,
                                         uint32_t bytes, uint32_t mbar) {
    asm volatile(
        "cp.async.bulk.shared::cta.global.mbarrier::complete_tx::bytes "
        "[%0], [%1], %2, [%3];"
        :: "r"(dst), "l"(src), "r"(bytes), "r"(mbar) : "memory");
}
__device__ __forceinline__ void fence_async_shared() {
    asm volatile("fence.proxy.async.shared::cta;" ::: "memory");
}
__device__ __forceinline__ void mbar_wait(uint32_t mbar, uint32_t parity) {
    asm volatile(
        "{\n\t"
        ".reg .pred P;\n\t"
        "WL_%=:\n\t"
        "mbarrier.try_wait.parity.acquire.cta.shared::cta.b64 P, [%0], %1, 0x989680;\n\t"
        "@P bra WD_%=;\n\t"
        "bra WL_%=;\n\t"
        "WD_%=:\n\t"
        "}"
        :: "r"(mbar), "r"(parity) : "memory");
}

__global__ __launch_bounds__(APB) void fl_tma_kernel(
    const float* __restrict__ cls,      // [B, A, C]
    const float* __restrict__ reg,      // [B, A, 4]
    const float* __restrict__ anchors,  // [1, A, 4]
    const float* __restrict__ ann,      // [B, M, 6]
    float* __restrict__ out)            // [2]
{
    extern __shared__ __align__(16) float s_buf[];   // 2 stages x CHF floats

    __shared__ float4 s_box[M];
    __shared__ float2 s_misc[M];         // x = area_b, y = class id
    __shared__ float  s_mask[APB];       // NEGW if anchor contributes, else 0
    __shared__ float  s_rc[APB / 32];
    __shared__ float  s_rr[APB / 32];
    __shared__ int    s_rp[APB / 32];
    __shared__ bool   s_last;
    __shared__ __align__(8) unsigned long long s_mbar[2];

    const int b    = blockIdx.y;
    const int a0   = blockIdx.x * APB;
    const int tid  = threadIdx.x;
    const int wid  = tid >> 5;
    const int lane = tid & 31;
    const int blk  = b * NTILES + blockIdx.x;
    const int nA   = min(APB, A - a0);      // 320 or 160; always multiple of 80
    const int nchunks = nA / CHA;           // 4 or 2

    const float* __restrict__ tile = cls + ((size_t)b * A + a0) * C;
    const uint32_t mb0 = s2u(&s_mbar[0]);
    const uint32_t mb1 = s2u(&s_mbar[1]);
    const uint32_t sb0 = s2u(&s_buf[0]);
    const uint32_t sb1 = s2u(&s_buf[CHF]);

    // mbarrier init + launch the first two bulk copies BEFORE the ALU phase:
    // the copy engine streams them while every warp does IoU work.
    if (tid == 0) {
        mbar_init(mb0, 1);
        mbar_init(mb1, 1);
    }
    // stage annotations
    if (tid < M) {
        const float* ap = ann + (b * M + tid) * 6;
        float x1 = ap[0], y1 = ap[1], x2 = ap[2], y2 = ap[3];
        const float cl = ap[4];
        float area = (x2 - x1) * (y2 - y1);
        if (cl == -1.0f) {
            // Invalid GT: far-away box -> inter == 0 always, area 0 ->
            // identical classification/argmax behavior to reference's iou=-1.
            x1 = 3e9f; y1 = 3e9f; x2 = 3e9f; y2 = 3e9f; area = 0.0f;
        }
        s_box[tid]  = make_float4(x1, y1, x2, y2);
        s_misc[tid] = make_float2(area, cl);
    }
    __syncthreads();   // mbarriers initialized, annotations staged

    if (tid == 0) {
        mbar_expect_tx(mb0, CHB);
        bulk_g2s(sb0, tile + 0 * CHF, CHB, mb0);
        mbar_expect_tx(mb1, CHB);
        bulk_g2s(sb1, tile + 1 * CHF, CHB, mb1);
    }

    // ================= phase 1: IoU assignment (overlapped with copies) ====
    float cls_partial = 0.0f;
    float reg_partial = 0.0f;
    int   pos_cnt = 0;

    const int a = a0 + tid;
    if (a < A) {
        const float4 av = *reinterpret_cast<const float4*>(anchors + a * 4);
        const float ax1 = av.x, ay1 = av.y, ax2 = av.z, ay2 = av.w;
        const float aw = ax2 - ax1;
        const float ah = ay2 - ay1;
        const float area_a = aw * ah;

        // IoU argmax via cross-multiplication (no division; ua >= area_a > 0)
        float b_in = -1.0f, b_ua = 1.0f;
        int   bi = 0;
        #pragma unroll 8
        for (int j = 0; j < M; j++) {
            const float4 g  = s_box[j];
            const float2 mi = s_misc[j];
            const float iw = fminf(ax2, g.z) - fmaxf(ax1, g.x);
            const float ih = fminf(ay2, g.w) - fmaxf(ay1, g.y);
            const float inter = fmaxf(iw, 0.0f) * fmaxf(ih, 0.0f);
            const float ua = (area_a + mi.x) - inter;
            if (inter * b_ua > b_in * ua) { b_in = inter; b_ua = ua; bi = j; }
        }

        const bool pos = (b_in >= 0.5f * b_ua);
        const bool ign = (!pos) && (b_in >= 0.4f * b_ua);
        s_mask[tid] = ign ? 0.0f : NEGW;

        if (pos) {
            pos_cnt = 1;
            const float4 g = s_box[bi];

            // positive-class correction: remove exactly the unmasked sweep
            // term, add the reference positive term.
            const int cid = (int)s_misc[bi].y;
            const float p_raw = cls[((size_t)b * A + a) * C + cid];
            const float sweep_term =
                NEGW * (p_raw * p_raw * __log2f(1.0f - p_raw));
            const float pc = fminf(fmaxf(p_raw, 1e-4f), 1.0f - 1e-4f);
            const float qc = 1.0f - pc;
            cls_partial += 0.25f * qc * qc * (-__logf(pc)) - sweep_term;

            // regression loss (smooth L1)
            float gw = g.z - g.x;
            float gh = g.w - g.y;
            const float gcx = g.x + 0.5f * gw;
            const float gcy = g.y + 0.5f * gh;
            gw = fmaxf(gw, 1.0f);
            gh = fmaxf(gh, 1.0f);
            const float acx = ax1 + 0.5f * aw;
            const float acy = ay1 + 0.5f * ah;
            const float t0 = ((gcx - acx) / aw) * 10.0f;
            const float t1 = ((gcy - acy) / ah) * 10.0f;
            const float t2 = __logf(gw / aw) * 5.0f;
            const float t3 = __logf(gh / ah) * 5.0f;
            const float4 r = *reinterpret_cast<const float4*>(reg + ((size_t)b * A + a) * 4);
            const float d0 = fabsf(t0 - r.x);
            const float d1 = fabsf(t1 - r.y);
            const float d2 = fabsf(t2 - r.z);
            const float d3 = fabsf(t3 - r.w);
            const float th = 1.0f / 9.0f;
            const float c2 = 0.5f / 9.0f;
            reg_partial  = (d0 <= th) ? 4.5f * d0 * d0 : d0 - c2;
            reg_partial += (d1 <= th) ? 4.5f * d1 * d1 : d1 - c2;
            reg_partial += (d2 <= th) ? 4.5f * d2 * d2 : d2 - c2;
            reg_partial += (d3 <= th) ? 4.5f * d3 * d3 : d3 - c2;
        }
    } else {
        s_mask[tid] = 0.0f;
    }
    __syncthreads();   // masks visible to all consumers

    // ================= phase 2: double-buffered bulk-copy pipeline =========
    const int mbase = tid / 20;   // APB = 16*20: anchor(tid+320j) = mbase+16j
    float acc0 = 0.f, acc1 = 0.f;

    #pragma unroll
    for (int k = 0; k < 4; k++) {
        if (k >= nchunks) break;
        const uint32_t mb = (k & 1) ? mb1 : mb0;
        const float4* sb4 = reinterpret_cast<const float4*>(
            (k & 1) ? (s_buf + CHF) : s_buf);
        mbar_wait(mb, (k >> 1) & 1);

        const int moff = k * CHA;
        #pragma unroll
        for (int j = 0; j < 5; j++) {
            const float4 v = sb4[tid + j * APB];
            const float m = s_mask[moff + mbase + 16 * j];
            const float l0 = __log2f(1.0f - v.x);
            const float l1 = __log2f(1.0f - v.y);
            const float l2 = __log2f(1.0f - v.z);
            const float l3 = __log2f(1.0f - v.w);
            const float s = fmaf(v.x * v.x, l0, fmaf(v.y * v.y, l1,
                            fmaf(v.z * v.z, l2, (v.w * v.w) * l3)));
            if (j & 1) acc1 = fmaf(m, s, acc1);
            else       acc0 = fmaf(m, s, acc0);
        }

        if (k + 2 < nchunks) {
            __syncthreads();   // all reads of this stage done
            if (tid == 0) {
                fence_async_shared();
                mbar_expect_tx(mb, CHB);
                bulk_g2s((k & 1) ? sb1 : sb0, tile + (k + 2) * CHF, CHB, mb);
            }
        }
    }
    cls_partial += acc0 + acc1;

    // Block reduction -> per-CTA partials
    float cv = cls_partial;
    float rv = reg_partial;
    int   pv = pos_cnt;
    #pragma unroll
    for (int o = 16; o > 0; o >>= 1) {
        cv += __shfl_down_sync(0xFFFFFFFFu, cv, o);
        rv += __shfl_down_sync(0xFFFFFFFFu, rv, o);
        pv += __shfl_down_sync(0xFFFFFFFFu, pv, o);
    }
    if (lane == 0) { s_rc[wid] = cv; s_rr[wid] = rv; s_rp[wid] = pv; }
    __syncthreads();

    if (tid == 0) {
        float c = 0.0f, r = 0.0f;
        int p = 0;
        #pragma unroll
        for (int i = 0; i < APB / 32; i++) { c += s_rc[i]; r += s_rr[i]; p += s_rp[i]; }
        g_cls_part[blk] = c;
        g_reg_part[blk] = r;
        g_pos_part[blk] = p;
        __threadfence();
        const unsigned int t = atomicAdd(&g_ticket, 1u);
        s_last = (t == (unsigned int)(NBLK - 1));
    }
    __syncthreads();

    // Last CTA reduces all per-CTA partials and writes the output.
    if (s_last) {
        __shared__ double f_c[B][APB / 32];
        __shared__ double f_r[B][APB / 32];
        __shared__ int    f_p[B][APB / 32];

        #pragma unroll
        for (int img = 0; img < B; img++) {
            double c = 0.0, r = 0.0;
            int p = 0;
            for (int i = tid; i < NTILES; i += APB) {
                const int idx = img * NTILES + i;
                c += (double)g_cls_part[idx];
                r += (double)g_reg_part[idx];
                p += g_pos_part[idx];
            }
            #pragma unroll
            for (int o = 16; o > 0; o >>= 1) {
                c += __shfl_down_sync(0xFFFFFFFFu, c, o);
                r += __shfl_down_sync(0xFFFFFFFFu, r, o);
                p += __shfl_down_sync(0xFFFFFFFFu, p, o);
            }
            if (lane == 0) { f_c[img][wid] = c; f_r[img][wid] = r; f_p[img][wid] = p; }
        }
        __syncthreads();
        if (tid == 0) {
            double cl = 0.0, rl = 0.0;
            #pragma unroll
            for (int img = 0; img < B; img++) {
                double c = 0.0, r = 0.0;
                int p = 0;
                #pragma unroll
                for (int i = 0; i < APB / 32; i++) {
                    c += f_c[img][i]; r += f_r[img][i]; p += f_p[img][i];
                }
                const double d = (p < 1) ? 1.0 : (double)p;
                cl += c / d;
                if (p > 0) rl += r / (4.0 * d);
            }
            out[0] = (float)(cl / (double)B);
            out[1] = (float)(rl / (double)B);
            g_ticket = 0;  // reset for the next graph replay
        }
    }
}

extern "C" void kernel_launch(void* const* d_in, const int* in_sizes, int n_in,
                              void* d_out, int out_size) {
    const float* cls = nullptr;
    const float* reg = nullptr;
    const float* anc = nullptr;
    const float* ann = nullptr;
    for (int i = 0; i < n_in; i++) {
        switch (in_sizes[i]) {
            case B * A * C:  cls = (const float*)d_in[i]; break;  // 64,000,000
            case B * A * 4:  reg = (const float*)d_in[i]; break;  //  3,200,000
            case A * 4:      anc = (const float*)d_in[i]; break;  //    400,000
            case B * M * 6:  ann = (const float*)d_in[i]; break;  //      1,536
            default: break;
        }
    }
    float* out = (float*)d_out;

    cudaFuncSetAttribute(fl_tma_kernel,
                         cudaFuncAttributeMaxDynamicSharedMemorySize, SMEM_DYN);
    dim3 grid(NTILES, B);
    fl_tma_kernel<<<grid, APB, SMEM_DYN>>>(cls, reg, anc, ann, out);
}